// round 1
// baseline (speedup 1.0000x reference)
#include <cuda_runtime.h>
#include <cuda_bf16.h>

#define N_NODES 50000
#define D 128
#define N_EDGES 800000
#define N_EVAL 100000

// ---------------- scratch (device globals; no allocation allowed) ----------
__device__ float g_bufA[N_NODES * D];   // GEMM outputs (h1, then h2)
__device__ float g_bufB[N_NODES * D];   // agg outputs (z1, then z2)
__device__ float g_dinv[N_NODES];
__device__ int   g_cnt[N_NODES];
__device__ int   g_fill[N_NODES];
__device__ int   g_rowptr[N_NODES + 1];
__device__ int   g_local[N_NODES];
__device__ int   g_sums[128];
__device__ int   g_csr_src[N_EDGES];
__device__ float g_csr_norm[N_EDGES];

// ---------------- CSR build ------------------------------------------------
__global__ void k_init() {
    int i = blockIdx.x * blockDim.x + threadIdx.x;
    if (i < N_NODES) { g_cnt[i] = 0; g_fill[i] = 0; }
}

__global__ void k_count(const int* __restrict__ dst) {
    int e = blockIdx.x * blockDim.x + threadIdx.x;
    if (e < N_EDGES) atomicAdd(&g_cnt[dst[e]], 1);
}

#define SCAN_CHUNK 512
__global__ void k_scan_part() {
    __shared__ int tmp[SCAN_CHUNK];
    int b = blockIdx.x, t = threadIdx.x;
    int i = b * SCAN_CHUNK + t;
    int v = (i < N_NODES) ? g_cnt[i] : 0;
    tmp[t] = v;
    __syncthreads();
    #pragma unroll
    for (int off = 1; off < SCAN_CHUNK; off <<= 1) {
        int x = (t >= off) ? tmp[t - off] : 0;
        __syncthreads();
        tmp[t] += x;
        __syncthreads();
    }
    if (i < N_NODES) g_local[i] = tmp[t];     // inclusive within chunk
    if (t == SCAN_CHUNK - 1) g_sums[b] = tmp[t];
}

__global__ void k_scan_tops(int nb) {
    if (threadIdx.x == 0) {
        int acc = 0;
        for (int i = 0; i < nb; i++) { int v = g_sums[i]; g_sums[i] = acc; acc += v; }
    }
}

__global__ void k_scan_add() {
    int i = blockIdx.x * blockDim.x + threadIdx.x;
    if (i < N_NODES) {
        int incl = g_local[i] + g_sums[i / SCAN_CHUNK];
        g_rowptr[i + 1] = incl;
        if (i == 0) g_rowptr[0] = 0;
        g_dinv[i] = rsqrtf((float)g_cnt[i] + 1.0f);
    }
}

__global__ void k_fill(const int* __restrict__ src, const int* __restrict__ dst) {
    int e = blockIdx.x * blockDim.x + threadIdx.x;
    if (e < N_EDGES) {
        int s = src[e], d = dst[e];
        int slot = atomicAdd(&g_fill[d], 1);
        int idx = g_rowptr[d] + slot;
        g_csr_src[idx] = s;
        g_csr_norm[idx] = g_dinv[s] * g_dinv[d];
    }
}

// ---------------- GEMM: H[n,128] = X[n,128] @ W[128,128] -------------------
#define TM 64
#define KC 32
__global__ void k_gemm(const float* __restrict__ X, const float* __restrict__ W,
                       float* __restrict__ H) {
    __shared__ float Xs[TM][KC + 1];
    __shared__ float Ws[KC][D];
    int row0 = blockIdx.x * TM;
    int tid = threadIdx.x;             // 256 threads
    int tx = tid & 31;                 // 4-col group
    int ty = tid >> 5;                 // 8-row group
    float acc[8][4] = {};

    for (int k0 = 0; k0 < D; k0 += KC) {
        for (int i = tid; i < TM * KC; i += 256) {
            int r = i / KC, c = i % KC;
            int gr = row0 + r;
            Xs[r][c] = (gr < N_NODES) ? X[gr * D + k0 + c] : 0.0f;
        }
        for (int i = tid; i < KC * D; i += 256) {
            int r = i >> 7, c = i & 127;
            Ws[r][c] = W[(k0 + r) * D + c];
        }
        __syncthreads();
        #pragma unroll
        for (int k = 0; k < KC; k++) {
            float4 b4 = *(const float4*)&Ws[k][tx * 4];
            #pragma unroll
            for (int i = 0; i < 8; i++) {
                float a = Xs[ty * 8 + i][k];
                acc[i][0] = fmaf(a, b4.x, acc[i][0]);
                acc[i][1] = fmaf(a, b4.y, acc[i][1]);
                acc[i][2] = fmaf(a, b4.z, acc[i][2]);
                acc[i][3] = fmaf(a, b4.w, acc[i][3]);
            }
        }
        __syncthreads();
    }
    #pragma unroll
    for (int i = 0; i < 8; i++) {
        int gr = row0 + ty * 8 + i;
        if (gr < N_NODES) {
            float4 v = {acc[i][0], acc[i][1], acc[i][2], acc[i][3]};
            *(float4*)(H + gr * D + tx * 4) = v;
        }
    }
}

// ---------------- Aggregation (gather via CSR, no float atomics) -----------
// Z[i] = sum_{e in-edges(i)} H[src_e]*norm_e + H[i]*dinv_i^2 + bias ; opt relu
__global__ void k_agg(const float* __restrict__ H, const float* __restrict__ bias,
                      float* __restrict__ Z, int relu_out) {
    int node = blockIdx.x * (blockDim.x >> 5) + (threadIdx.x >> 5);
    int lane = threadIdx.x & 31;
    if (node >= N_NODES) return;
    const float4* H4 = (const float4*)H;
    float di = g_dinv[node];
    float sl = di * di;
    float4 acc = H4[node * 32 + lane];
    acc.x *= sl; acc.y *= sl; acc.z *= sl; acc.w *= sl;
    int e0 = g_rowptr[node], e1 = g_rowptr[node + 1];
    for (int e = e0; e < e1; e++) {
        int s = g_csr_src[e];
        float nm = g_csr_norm[e];
        float4 v = H4[s * 32 + lane];
        acc.x = fmaf(v.x, nm, acc.x);
        acc.y = fmaf(v.y, nm, acc.y);
        acc.z = fmaf(v.z, nm, acc.z);
        acc.w = fmaf(v.w, nm, acc.w);
    }
    float4 b = ((const float4*)bias)[lane];
    acc.x += b.x; acc.y += b.y; acc.z += b.z; acc.w += b.w;
    if (relu_out) {
        acc.x = fmaxf(acc.x, 0.f); acc.y = fmaxf(acc.y, 0.f);
        acc.z = fmaxf(acc.z, 0.f); acc.w = fmaxf(acc.w, 0.f);
    }
    ((float4*)Z)[node * 32 + lane] = acc;
}

// ---------------- Scores ---------------------------------------------------
__global__ void k_score(const float* __restrict__ Z, const int* __restrict__ idx,
                        float* __restrict__ out) {
    int i = blockIdx.x * (blockDim.x >> 5) + (threadIdx.x >> 5);
    int lane = threadIdx.x & 31;
    if (i >= N_EVAL) return;
    int a = idx[i], b = idx[N_EVAL + i];
    const float4* Z4 = (const float4*)Z;
    float4 va = Z4[a * 32 + lane];
    float4 vb = Z4[b * 32 + lane];
    float s = va.x * vb.x + va.y * vb.y + va.z * vb.z + va.w * vb.w;
    #pragma unroll
    for (int off = 16; off; off >>= 1) s += __shfl_xor_sync(0xFFFFFFFFu, s, off);
    if (lane == 0) out[i] = s;
}

// ---------------- launch ---------------------------------------------------
extern "C" void kernel_launch(void* const* d_in, const int* in_sizes, int n_in,
                              void* d_out, int out_size) {
    const float* x   = (const float*)d_in[0];
    const float* W1  = (const float*)d_in[1];
    const float* b1  = (const float*)d_in[2];
    const float* W2  = (const float*)d_in[3];
    const float* b2  = (const float*)d_in[4];
    const int* ei    = (const int*)d_in[5];
    const int* pos   = (const int*)d_in[6];
    const int* neg   = (const int*)d_in[7];
    float* out = (float*)d_out;

    const int* src = ei;
    const int* dst = ei + N_EDGES;

    float *bufA, *bufB;
    cudaGetSymbolAddress((void**)&bufA, g_bufA);
    cudaGetSymbolAddress((void**)&bufB, g_bufB);

    int nb_scan = (N_NODES + SCAN_CHUNK - 1) / SCAN_CHUNK;  // 98

    // CSR build
    k_init<<<(N_NODES + 255) / 256, 256>>>();
    k_count<<<(N_EDGES + 255) / 256, 256>>>(dst);
    k_scan_part<<<nb_scan, SCAN_CHUNK>>>();
    k_scan_tops<<<1, 32>>>(nb_scan);
    k_scan_add<<<(N_NODES + 255) / 256, 256>>>();
    k_fill<<<(N_EDGES + 255) / 256, 256>>>(src, dst);

    int gemm_grid = (N_NODES + TM - 1) / TM;
    int agg_grid = (N_NODES + 7) / 8;      // 8 warps/block
    int sc_grid = (N_EVAL + 7) / 8;

    // Layer 1
    k_gemm<<<gemm_grid, 256>>>(x, W1, bufA);
    k_agg<<<agg_grid, 256>>>(bufA, b1, bufB, 1);
    // Layer 2
    k_gemm<<<gemm_grid, 256>>>(bufB, W2, bufA);
    k_agg<<<agg_grid, 256>>>(bufA, b2, bufB, 0);
    // Scores
    k_score<<<sc_grid, 256>>>(bufB, pos, out);
    k_score<<<sc_grid, 256>>>(bufB, neg, out + N_EVAL);
}

// round 2
// speedup vs baseline: 1.1336x; 1.1336x over previous
#include <cuda_runtime.h>
#include <cuda_bf16.h>

#define N_NODES 50000
#define D 128
#define N_EDGES 800000
#define N_EVAL 100000

// ---------------- scratch (device globals; no allocation allowed) ----------
__device__ float g_bufA[N_NODES * D];   // GEMM outputs (h1, then h2)
__device__ float g_bufB[N_NODES * D];   // agg outputs (z1, then z2)
__device__ float g_dinv[N_NODES];
__device__ int   g_cnt[N_NODES];
__device__ int   g_fill[N_NODES];
__device__ int   g_rowptr[N_NODES + 1];
__device__ int   g_local[N_NODES];
__device__ int   g_sums[128];
__device__ int   g_csr_src[N_EDGES];
__device__ float g_csr_norm[N_EDGES];

// ---------------- f32x2 helpers --------------------------------------------
__device__ __forceinline__ void ffma2(unsigned long long& d, unsigned long long a,
                                      unsigned long long b) {
    asm("fma.rn.f32x2 %0, %1, %2, %0;" : "+l"(d) : "l"(a), "l"(b));
}
__device__ __forceinline__ unsigned long long pack2(float x) {
    unsigned long long r;
    asm("mov.b64 %0, {%1, %1};" : "=l"(r) : "f"(x));
    return r;
}
__device__ __forceinline__ void unpack2(float& lo, float& hi, unsigned long long v) {
    asm("mov.b64 {%0, %1}, %2;" : "=f"(lo), "=f"(hi) : "l"(v));
}

// ---------------- CSR build ------------------------------------------------
__global__ void k_count(const int* __restrict__ dst) {
    int e = blockIdx.x * blockDim.x + threadIdx.x;
    if (e < N_EDGES) atomicAdd(&g_cnt[dst[e]], 1);
}

#define SCAN_CHUNK 512
__global__ void k_scan_part() {
    __shared__ int tmp[SCAN_CHUNK];
    int b = blockIdx.x, t = threadIdx.x;
    int i = b * SCAN_CHUNK + t;
    int v = (i < N_NODES) ? g_cnt[i] : 0;
    tmp[t] = v;
    __syncthreads();
    #pragma unroll
    for (int off = 1; off < SCAN_CHUNK; off <<= 1) {
        int x = (t >= off) ? tmp[t - off] : 0;
        __syncthreads();
        tmp[t] += x;
        __syncthreads();
    }
    if (i < N_NODES) g_local[i] = tmp[t];     // inclusive within chunk
    if (t == SCAN_CHUNK - 1) g_sums[b] = tmp[t];
}

__global__ void k_scan_tops(int nb) {
    __shared__ int tmp[128];
    int t = threadIdx.x;
    int v = (t < nb) ? g_sums[t] : 0;
    tmp[t] = v;
    __syncthreads();
    #pragma unroll
    for (int off = 1; off < 128; off <<= 1) {
        int x = (t >= off) ? tmp[t - off] : 0;
        __syncthreads();
        tmp[t] += x;
        __syncthreads();
    }
    if (t < nb) g_sums[t] = tmp[t] - v;       // exclusive
}

__global__ void k_scan_add() {
    int i = blockIdx.x * blockDim.x + threadIdx.x;
    if (i < N_NODES) {
        int incl = g_local[i] + g_sums[i / SCAN_CHUNK];
        g_rowptr[i + 1] = incl;
        if (i == 0) g_rowptr[0] = 0;
        g_dinv[i] = rsqrtf((float)g_cnt[i] + 1.0f);
    }
}

__global__ void k_fill(const int* __restrict__ src, const int* __restrict__ dst) {
    int e = blockIdx.x * blockDim.x + threadIdx.x;
    if (e < N_EDGES) {
        int s = src[e], d = dst[e];
        int slot = atomicAdd(&g_fill[d], 1);
        int idx = g_rowptr[d] + slot;
        g_csr_src[idx] = s;
        g_csr_norm[idx] = g_dinv[s] * g_dinv[d];
    }
}

// ---------------- GEMM: H[n,128] = X[n,128] @ W[128,128] (f32x2 FFMA2) -----
#define TM 64
#define KC 32
#define XT_PITCH 66   // even (8B-aligned pairs), 2-way STS conflict only
__global__ void k_gemm(const float* __restrict__ X, const float* __restrict__ W,
                       float* __restrict__ H) {
    __shared__ float Xt[KC][XT_PITCH];    // transposed: Xt[k][row]
    __shared__ float Ws[KC][D];
    int row0 = blockIdx.x * TM;
    int tid = threadIdx.x;                // 256 threads
    int tx = tid & 31;                    // column group: 4 cols each
    int ty = tid >> 5;                    // row group: 8 rows each
    unsigned long long acc[4][4];         // [rowpair][col], f32x2 over rows
    #pragma unroll
    for (int p = 0; p < 4; p++)
        #pragma unroll
        for (int c = 0; c < 4; c++) acc[p][c] = 0ull;

    for (int k0 = 0; k0 < D; k0 += KC) {
        // Load X tile transposed. 64 rows x 32 cols = 512 float4 loads.
        for (int i = tid; i < (TM * KC) / 4; i += 256) {
            int r = i >> 3;               // 0..63
            int c4 = i & 7;               // 0..7
            int gr = row0 + r;
            float4 v = (gr < N_NODES) ? *(const float4*)(X + gr * D + k0 + c4 * 4)
                                      : make_float4(0.f, 0.f, 0.f, 0.f);
            Xt[c4 * 4 + 0][r] = v.x;
            Xt[c4 * 4 + 1][r] = v.y;
            Xt[c4 * 4 + 2][r] = v.z;
            Xt[c4 * 4 + 3][r] = v.w;
        }
        // Load W tile (row-major).
        for (int i = tid; i < (KC * D) / 4; i += 256) {
            int r = i >> 5, c4 = i & 31;
            *(float4*)&Ws[r][c4 * 4] = *(const float4*)(W + (k0 + r) * D + c4 * 4);
        }
        __syncthreads();
        #pragma unroll
        for (int k = 0; k < KC; k++) {
            float4 b4 = *(const float4*)&Ws[k][tx * 4];
            unsigned long long b0 = pack2(b4.x), b1 = pack2(b4.y);
            unsigned long long b2 = pack2(b4.z), b3 = pack2(b4.w);
            #pragma unroll
            for (int p = 0; p < 4; p++) {
                unsigned long long a =
                    *(const unsigned long long*)&Xt[k][ty * 8 + 2 * p];  // broadcast
                ffma2(acc[p][0], a, b0);
                ffma2(acc[p][1], a, b1);
                ffma2(acc[p][2], a, b2);
                ffma2(acc[p][3], a, b3);
            }
        }
        __syncthreads();
    }
    #pragma unroll
    for (int p = 0; p < 4; p++) {
        float lo0, hi0, lo1, hi1, lo2, hi2, lo3, hi3;
        unpack2(lo0, hi0, acc[p][0]);
        unpack2(lo1, hi1, acc[p][1]);
        unpack2(lo2, hi2, acc[p][2]);
        unpack2(lo3, hi3, acc[p][3]);
        int gr0 = row0 + ty * 8 + 2 * p;
        if (gr0 < N_NODES) {
            float4 v = {lo0, lo1, lo2, lo3};
            *(float4*)(H + gr0 * D + tx * 4) = v;
        }
        if (gr0 + 1 < N_NODES) {
            float4 v = {hi0, hi1, hi2, hi3};
            *(float4*)(H + (gr0 + 1) * D + tx * 4) = v;
        }
    }
}

// ---------------- Aggregation (gather via CSR, no float atomics) -----------
__global__ void k_agg(const float* __restrict__ H, const float* __restrict__ bias,
                      float* __restrict__ Z, int relu_out) {
    int node = blockIdx.x * (blockDim.x >> 5) + (threadIdx.x >> 5);
    int lane = threadIdx.x & 31;
    if (node >= N_NODES) return;
    const float4* H4 = (const float4*)H;
    float di = g_dinv[node];
    float sl = di * di;
    float4 acc = H4[node * 32 + lane];
    acc.x *= sl; acc.y *= sl; acc.z *= sl; acc.w *= sl;
    int e0 = g_rowptr[node], e1 = g_rowptr[node + 1];
    for (int e = e0; e < e1; e++) {
        int s = g_csr_src[e];
        float nm = g_csr_norm[e];
        float4 v = H4[s * 32 + lane];
        acc.x = fmaf(v.x, nm, acc.x);
        acc.y = fmaf(v.y, nm, acc.y);
        acc.z = fmaf(v.z, nm, acc.z);
        acc.w = fmaf(v.w, nm, acc.w);
    }
    float4 b = ((const float4*)bias)[lane];
    acc.x += b.x; acc.y += b.y; acc.z += b.z; acc.w += b.w;
    if (relu_out) {
        acc.x = fmaxf(acc.x, 0.f); acc.y = fmaxf(acc.y, 0.f);
        acc.z = fmaxf(acc.z, 0.f); acc.w = fmaxf(acc.w, 0.f);
    }
    ((float4*)Z)[node * 32 + lane] = acc;
}

// ---------------- Scores (pos + neg fused) ---------------------------------
__global__ void k_score2(const float* __restrict__ Z, const int* __restrict__ pos,
                         const int* __restrict__ neg, float* __restrict__ out) {
    int i = blockIdx.x * (blockDim.x >> 5) + (threadIdx.x >> 5);
    int lane = threadIdx.x & 31;
    if (i >= 2 * N_EVAL) return;
    const int* idx = (i < N_EVAL) ? pos : neg;
    int j = (i < N_EVAL) ? i : i - N_EVAL;
    int a = idx[j], b = idx[N_EVAL + j];
    const float4* Z4 = (const float4*)Z;
    float4 va = Z4[a * 32 + lane];
    float4 vb = Z4[b * 32 + lane];
    float s = va.x * vb.x + va.y * vb.y + va.z * vb.z + va.w * vb.w;
    #pragma unroll
    for (int off = 16; off; off >>= 1) s += __shfl_xor_sync(0xFFFFFFFFu, s, off);
    if (lane == 0) out[i] = s;
}

// ---------------- launch ---------------------------------------------------
extern "C" void kernel_launch(void* const* d_in, const int* in_sizes, int n_in,
                              void* d_out, int out_size) {
    const float* x   = (const float*)d_in[0];
    const float* W1  = (const float*)d_in[1];
    const float* b1  = (const float*)d_in[2];
    const float* W2  = (const float*)d_in[3];
    const float* b2  = (const float*)d_in[4];
    const int* ei    = (const int*)d_in[5];
    const int* pos   = (const int*)d_in[6];
    const int* neg   = (const int*)d_in[7];
    float* out = (float*)d_out;

    const int* src = ei;
    const int* dst = ei + N_EDGES;

    float *bufA, *bufB;
    int *cntp, *fillp;
    cudaGetSymbolAddress((void**)&bufA, g_bufA);
    cudaGetSymbolAddress((void**)&bufB, g_bufB);
    cudaGetSymbolAddress((void**)&cntp, g_cnt);
    cudaGetSymbolAddress((void**)&fillp, g_fill);

    int nb_scan = (N_NODES + SCAN_CHUNK - 1) / SCAN_CHUNK;  // 98

    // CSR build
    cudaMemsetAsync(cntp, 0, N_NODES * sizeof(int));
    cudaMemsetAsync(fillp, 0, N_NODES * sizeof(int));
    k_count<<<(N_EDGES + 255) / 256, 256>>>(dst);
    k_scan_part<<<nb_scan, SCAN_CHUNK>>>();
    k_scan_tops<<<1, 128>>>(nb_scan);
    k_scan_add<<<(N_NODES + 255) / 256, 256>>>();
    k_fill<<<(N_EDGES + 255) / 256, 256>>>(src, dst);

    int gemm_grid = (N_NODES + TM - 1) / TM;
    int agg_grid = (N_NODES + 7) / 8;       // 8 warps/block
    int sc_grid = (2 * N_EVAL + 7) / 8;

    // Layer 1
    k_gemm<<<gemm_grid, 256>>>(x, W1, bufA);
    k_agg<<<agg_grid, 256>>>(bufA, b1, bufB, 1);
    // Layer 2
    k_gemm<<<gemm_grid, 256>>>(bufB, W2, bufA);
    k_agg<<<agg_grid, 256>>>(bufA, b2, bufB, 0);
    // Scores
    k_score2<<<sc_grid, 256>>>(bufB, pos, neg, out);
}

// round 3
// speedup vs baseline: 1.1894x; 1.0492x over previous
#include <cuda_runtime.h>
#include <cuda_bf16.h>

#define N_NODES 50000
#define D 128
#define N_EDGES 800000
#define N_EVAL 100000

// ---------------- scratch (device globals; no allocation allowed) ----------
__device__ float g_bufA[N_NODES * D];   // GEMM outputs (h1, then h2)
__device__ float g_bufB[N_NODES * D];   // agg outputs (z1, then z2)
__device__ float g_dinv[N_NODES];
__device__ int   g_cnt[N_NODES];        // zeroed by k_scan_addtops each run
__device__ int   g_fill[N_NODES];       // zeroed by k_agg each run
__device__ int   g_rowptr[N_NODES + 1];
__device__ int   g_local[N_NODES];
__device__ int   g_sums[128];
__device__ int   g_csr_src[N_EDGES];
__device__ float g_csr_norm[N_EDGES];

// ---------------- f32x2 helpers --------------------------------------------
__device__ __forceinline__ void ffma2(unsigned long long& d, unsigned long long a,
                                      unsigned long long b) {
    asm("fma.rn.f32x2 %0, %1, %2, %0;" : "+l"(d) : "l"(a), "l"(b));
}
__device__ __forceinline__ unsigned long long pack2(float x) {
    unsigned long long r;
    asm("mov.b64 %0, {%1, %1};" : "=l"(r) : "f"(x));
    return r;
}
__device__ __forceinline__ void unpack2(float& lo, float& hi, unsigned long long v) {
    asm("mov.b64 {%0, %1}, %2;" : "=f"(lo), "=f"(hi) : "l"(v));
}

// ---------------- GEMM device body (f32x2 FFMA2) ---------------------------
#define TM 64
#define KC 32
#define XT_PITCH 66
#define GEMM_GRID ((N_NODES + TM - 1) / TM)     // 782

struct GemmSmem {
    float Xt[KC][XT_PITCH];
    float Ws[KC][D];
};

__device__ __forceinline__ void gemm_body(GemmSmem& s,
                                          const float* __restrict__ X,
                                          const float* __restrict__ W,
                                          float* __restrict__ H, int bid) {
    int row0 = bid * TM;
    int tid = threadIdx.x;                // 256 threads
    int tx = tid & 31;                    // column group: 4 cols each
    int ty = tid >> 5;                    // row group: 8 rows each
    unsigned long long acc[4][4];
    #pragma unroll
    for (int p = 0; p < 4; p++)
        #pragma unroll
        for (int c = 0; c < 4; c++) acc[p][c] = 0ull;

    for (int k0 = 0; k0 < D; k0 += KC) {
        for (int i = tid; i < (TM * KC) / 4; i += 256) {
            int r = i >> 3;               // 0..63
            int c4 = i & 7;               // 0..7
            int gr = row0 + r;
            float4 v = (gr < N_NODES) ? *(const float4*)(X + gr * D + k0 + c4 * 4)
                                      : make_float4(0.f, 0.f, 0.f, 0.f);
            s.Xt[c4 * 4 + 0][r] = v.x;
            s.Xt[c4 * 4 + 1][r] = v.y;
            s.Xt[c4 * 4 + 2][r] = v.z;
            s.Xt[c4 * 4 + 3][r] = v.w;
        }
        for (int i = tid; i < (KC * D) / 4; i += 256) {
            int r = i >> 5, c4 = i & 31;
            *(float4*)&s.Ws[r][c4 * 4] = *(const float4*)(W + (k0 + r) * D + c4 * 4);
        }
        __syncthreads();
        #pragma unroll
        for (int k = 0; k < KC; k++) {
            float4 b4 = *(const float4*)&s.Ws[k][tx * 4];
            unsigned long long b0 = pack2(b4.x), b1 = pack2(b4.y);
            unsigned long long b2 = pack2(b4.z), b3 = pack2(b4.w);
            #pragma unroll
            for (int p = 0; p < 4; p++) {
                unsigned long long a =
                    *(const unsigned long long*)&s.Xt[k][ty * 8 + 2 * p];
                ffma2(acc[p][0], a, b0);
                ffma2(acc[p][1], a, b1);
                ffma2(acc[p][2], a, b2);
                ffma2(acc[p][3], a, b3);
            }
        }
        __syncthreads();
    }
    #pragma unroll
    for (int p = 0; p < 4; p++) {
        float lo0, hi0, lo1, hi1, lo2, hi2, lo3, hi3;
        unpack2(lo0, hi0, acc[p][0]);
        unpack2(lo1, hi1, acc[p][1]);
        unpack2(lo2, hi2, acc[p][2]);
        unpack2(lo3, hi3, acc[p][3]);
        int gr0 = row0 + ty * 8 + 2 * p;
        if (gr0 < N_NODES) {
            float4 v = {lo0, lo1, lo2, lo3};
            *(float4*)(H + gr0 * D + tx * 4) = v;
        }
        if (gr0 + 1 < N_NODES) {
            float4 v = {hi0, hi1, hi2, hi3};
            *(float4*)(H + (gr0 + 1) * D + tx * 4) = v;
        }
    }
}

// ---------------- Fused: gemm1 (even blocks) + edge count (odd blocks) -----
#define COUNT_GRID GEMM_GRID            // 782 blocks * 256 threads; 4 edges/thread
__global__ void k_gemm1_count(const float* __restrict__ X, const float* __restrict__ W,
                              float* __restrict__ H, const int* __restrict__ dst) {
    __shared__ GemmSmem s;
    int bid = blockIdx.x >> 1;
    if ((blockIdx.x & 1) == 0) {
        gemm_body(s, X, W, H, bid);
    } else {
        // count: 4 edges per thread via int4 (dst is 16B aligned: 800000*4 % 16 == 0)
        int base = (bid * 256 + threadIdx.x) * 4;
        if (base + 3 < N_EDGES) {
            int4 d4 = *(const int4*)(dst + base);
            atomicAdd(&g_cnt[d4.x], 1);
            atomicAdd(&g_cnt[d4.y], 1);
            atomicAdd(&g_cnt[d4.z], 1);
            atomicAdd(&g_cnt[d4.w], 1);
        } else {
            for (int e = base; e < N_EDGES; e++) atomicAdd(&g_cnt[dst[e]], 1);
        }
    }
}

// ---------------- scan -----------------------------------------------------
#define SCAN_CHUNK 512
#define NB_SCAN ((N_NODES + SCAN_CHUNK - 1) / SCAN_CHUNK)   // 98
__global__ void k_scan_part() {
    __shared__ int tmp[SCAN_CHUNK];
    int b = blockIdx.x, t = threadIdx.x;
    int i = b * SCAN_CHUNK + t;
    int v = (i < N_NODES) ? g_cnt[i] : 0;
    tmp[t] = v;
    __syncthreads();
    #pragma unroll
    for (int off = 1; off < SCAN_CHUNK; off <<= 1) {
        int x = (t >= off) ? tmp[t - off] : 0;
        __syncthreads();
        tmp[t] += x;
        __syncthreads();
    }
    if (i < N_NODES) g_local[i] = tmp[t];     // inclusive within chunk
    if (t == SCAN_CHUNK - 1) g_sums[b] = tmp[t];
}

// Each block redundantly scans the 98 chunk sums in smem, then finishes
// rowptr/dinv, and zeroes g_cnt for the next replay.
__global__ void k_scan_addtops() {
    __shared__ int tops[128];
    int t = threadIdx.x;
    if (t < 128) tops[t] = (t < NB_SCAN) ? g_sums[t] : 0;
    __syncthreads();
    #pragma unroll
    for (int off = 1; off < 128; off <<= 1) {
        int x = (t < 128 && t >= off) ? tops[t - off] : 0;
        __syncthreads();
        if (t < 128) tops[t] += x;
        __syncthreads();
    }
    int i = blockIdx.x * blockDim.x + t;
    if (i < N_NODES) {
        int chunk = i / SCAN_CHUNK;
        int excl = (chunk > 0) ? tops[chunk - 1] : 0;
        g_rowptr[i + 1] = g_local[i] + excl;
        if (i == 0) g_rowptr[0] = 0;
        g_dinv[i] = rsqrtf((float)g_cnt[i] + 1.0f);
        g_cnt[i] = 0;                          // ready for next replay
    }
}

__global__ void k_fill(const int* __restrict__ src, const int* __restrict__ dst) {
    int e = blockIdx.x * blockDim.x + threadIdx.x;
    if (e < N_EDGES) {
        int s = src[e], d = dst[e];
        int slot = atomicAdd(&g_fill[d], 1);
        int idx = g_rowptr[d] + slot;
        g_csr_src[idx] = s;
        g_csr_norm[idx] = g_dinv[s] * g_dinv[d];
    }
}

// ---------------- GEMM standalone (layer 2) --------------------------------
__global__ void k_gemm(const float* __restrict__ X, const float* __restrict__ W,
                       float* __restrict__ H) {
    __shared__ GemmSmem s;
    gemm_body(s, X, W, H, blockIdx.x);
}

// ---------------- Aggregation (gather via CSR, no float atomics) -----------
__global__ void k_agg(const float* __restrict__ H, const float* __restrict__ bias,
                      float* __restrict__ Z, int relu_out) {
    int node = blockIdx.x * (blockDim.x >> 5) + (threadIdx.x >> 5);
    int lane = threadIdx.x & 31;
    if (node >= N_NODES) return;
    const float4* H4 = (const float4*)H;
    float di = g_dinv[node];
    float sl = di * di;
    float4 acc = H4[node * 32 + lane];
    acc.x *= sl; acc.y *= sl; acc.z *= sl; acc.w *= sl;
    int e0 = g_rowptr[node], e1 = g_rowptr[node + 1];
    #pragma unroll 2
    for (int e = e0; e < e1; e++) {
        int s = g_csr_src[e];
        float nm = g_csr_norm[e];
        float4 v = H4[s * 32 + lane];
        acc.x = fmaf(v.x, nm, acc.x);
        acc.y = fmaf(v.y, nm, acc.y);
        acc.z = fmaf(v.z, nm, acc.z);
        acc.w = fmaf(v.w, nm, acc.w);
    }
    float4 b = ((const float4*)bias)[lane];
    acc.x += b.x; acc.y += b.y; acc.z += b.z; acc.w += b.w;
    if (relu_out) {
        acc.x = fmaxf(acc.x, 0.f); acc.y = fmaxf(acc.y, 0.f);
        acc.z = fmaxf(acc.z, 0.f); acc.w = fmaxf(acc.w, 0.f);
    }
    ((float4*)Z)[node * 32 + lane] = acc;
    if (lane == 0) g_fill[node] = 0;           // ready for next replay's k_fill
}

// ---------------- Scores (pos + neg fused) ---------------------------------
__global__ void k_score2(const float* __restrict__ Z, const int* __restrict__ pos,
                         const int* __restrict__ neg, float* __restrict__ out) {
    int i = blockIdx.x * (blockDim.x >> 5) + (threadIdx.x >> 5);
    int lane = threadIdx.x & 31;
    if (i >= 2 * N_EVAL) return;
    const int* idx = (i < N_EVAL) ? pos : neg;
    int j = (i < N_EVAL) ? i : i - N_EVAL;
    int a = idx[j], b = idx[N_EVAL + j];
    const float4* Z4 = (const float4*)Z;
    float4 va = Z4[a * 32 + lane];
    float4 vb = Z4[b * 32 + lane];
    float s = va.x * vb.x + va.y * vb.y + va.z * vb.z + va.w * vb.w;
    #pragma unroll
    for (int off = 16; off; off >>= 1) s += __shfl_xor_sync(0xFFFFFFFFu, s, off);
    if (lane == 0) out[i] = s;
}

// ---------------- launch ---------------------------------------------------
extern "C" void kernel_launch(void* const* d_in, const int* in_sizes, int n_in,
                              void* d_out, int out_size) {
    const float* x   = (const float*)d_in[0];
    const float* W1  = (const float*)d_in[1];
    const float* b1  = (const float*)d_in[2];
    const float* W2  = (const float*)d_in[3];
    const float* b2  = (const float*)d_in[4];
    const int* ei    = (const int*)d_in[5];
    const int* pos   = (const int*)d_in[6];
    const int* neg   = (const int*)d_in[7];
    float* out = (float*)d_out;

    const int* src = ei;
    const int* dst = ei + N_EDGES;

    float *bufA, *bufB;
    cudaGetSymbolAddress((void**)&bufA, g_bufA);
    cudaGetSymbolAddress((void**)&bufB, g_bufB);

    int agg_grid = (N_NODES + 7) / 8;       // 8 warps/block
    int sc_grid = (2 * N_EVAL + 7) / 8;

    // (1) gemm1 overlapped with edge counting (block specialization)
    k_gemm1_count<<<2 * GEMM_GRID, 256>>>(x, W1, bufA, dst);
    // (2,3) scan -> rowptr + dinv (+ zero g_cnt)
    k_scan_part<<<NB_SCAN, SCAN_CHUNK>>>();
    k_scan_addtops<<<(N_NODES + 255) / 256, 256>>>();
    // (4) CSR fill
    k_fill<<<(N_EDGES + 255) / 256, 256>>>(src, dst);
    // (5) Layer 1 aggregation (+ zero g_fill)
    k_agg<<<agg_grid, 256>>>(bufA, b1, bufB, 1);
    // (6) Layer 2 GEMM  <-- ncu -s 5 -c 1 profiles this launch
    k_gemm<<<GEMM_GRID, 256>>>(bufB, W2, bufA);
    // (7) Layer 2 aggregation
    k_agg<<<agg_grid, 256>>>(bufA, b2, bufB, 0);
    // (8) Scores
    k_score2<<<sc_grid, 256>>>(bufB, pos, neg, out);
}

// round 4
// speedup vs baseline: 1.2024x; 1.0110x over previous
#include <cuda_runtime.h>
#include <cuda_bf16.h>

#define N_NODES 50000
#define D 128
#define N_EDGES 800000
#define N_EVAL 100000

// ---------------- scratch (device globals; no allocation allowed) ----------
__device__ float g_bufA[N_NODES * D];   // GEMM outputs (h1, then h2)
__device__ float g_bufB[N_NODES * D];   // agg outputs (z1, then z2)
__device__ float g_dinv[N_NODES];
__device__ int   g_cnt[N_NODES];        // zeroed by k_scan each run
__device__ int   g_rowptr[N_NODES + 1];
__device__ int   g_slot[N_EDGES];       // per-edge slot from count phase
__device__ int2  g_csr[N_EDGES];        // interleaved {src, norm_bits}

// ---------------- f32x2 helpers --------------------------------------------
__device__ __forceinline__ void ffma2(unsigned long long& d, unsigned long long a,
                                      unsigned long long b) {
    asm("fma.rn.f32x2 %0, %1, %2, %0;" : "+l"(d) : "l"(a), "l"(b));
}
__device__ __forceinline__ unsigned long long pack2(float x) {
    unsigned long long r;
    asm("mov.b64 %0, {%1, %1};" : "=l"(r) : "f"(x));
    return r;
}
__device__ __forceinline__ void unpack2(float& lo, float& hi, unsigned long long v) {
    asm("mov.b64 {%0, %1}, %2;" : "=f"(lo), "=f"(hi) : "l"(v));
}

// ---------------- GEMM device body (f32x2 FFMA2) ---------------------------
#define TM 64
#define KC 32
#define XT_PITCH 66
#define GEMM_GRID ((N_NODES + TM - 1) / TM)     // 782

struct GemmSmem {
    float Xt[KC][XT_PITCH];
    float Ws[KC][D];
};

__device__ __forceinline__ void gemm_body(GemmSmem& s,
                                          const float* __restrict__ X,
                                          const float* __restrict__ W,
                                          float* __restrict__ H, int bid) {
    int row0 = bid * TM;
    int tid = threadIdx.x;                // 256 threads
    int tx = tid & 31;                    // column group: 4 cols each
    int ty = tid >> 5;                    // row group: 8 rows each
    unsigned long long acc[4][4];
    #pragma unroll
    for (int p = 0; p < 4; p++)
        #pragma unroll
        for (int c = 0; c < 4; c++) acc[p][c] = 0ull;

    for (int k0 = 0; k0 < D; k0 += KC) {
        for (int i = tid; i < (TM * KC) / 4; i += 256) {
            int r = i >> 3;               // 0..63
            int c4 = i & 7;               // 0..7
            int gr = row0 + r;
            float4 v = (gr < N_NODES) ? *(const float4*)(X + gr * D + k0 + c4 * 4)
                                      : make_float4(0.f, 0.f, 0.f, 0.f);
            s.Xt[c4 * 4 + 0][r] = v.x;
            s.Xt[c4 * 4 + 1][r] = v.y;
            s.Xt[c4 * 4 + 2][r] = v.z;
            s.Xt[c4 * 4 + 3][r] = v.w;
        }
        for (int i = tid; i < (KC * D) / 4; i += 256) {
            int r = i >> 5, c4 = i & 31;
            *(float4*)&s.Ws[r][c4 * 4] = *(const float4*)(W + (k0 + r) * D + c4 * 4);
        }
        __syncthreads();
        #pragma unroll
        for (int k = 0; k < KC; k++) {
            float4 b4 = *(const float4*)&s.Ws[k][tx * 4];
            unsigned long long b0 = pack2(b4.x), b1 = pack2(b4.y);
            unsigned long long b2 = pack2(b4.z), b3 = pack2(b4.w);
            #pragma unroll
            for (int p = 0; p < 4; p++) {
                unsigned long long a =
                    *(const unsigned long long*)&s.Xt[k][ty * 8 + 2 * p];
                ffma2(acc[p][0], a, b0);
                ffma2(acc[p][1], a, b1);
                ffma2(acc[p][2], a, b2);
                ffma2(acc[p][3], a, b3);
            }
        }
        __syncthreads();
    }
    #pragma unroll
    for (int p = 0; p < 4; p++) {
        float lo0, hi0, lo1, hi1, lo2, hi2, lo3, hi3;
        unpack2(lo0, hi0, acc[p][0]);
        unpack2(lo1, hi1, acc[p][1]);
        unpack2(lo2, hi2, acc[p][2]);
        unpack2(lo3, hi3, acc[p][3]);
        int gr0 = row0 + ty * 8 + 2 * p;
        if (gr0 < N_NODES) {
            float4 v = {lo0, lo1, lo2, lo3};
            *(float4*)(H + gr0 * D + tx * 4) = v;
        }
        if (gr0 + 1 < N_NODES) {
            float4 v = {hi0, hi1, hi2, hi3};
            *(float4*)(H + (gr0 + 1) * D + tx * 4) = v;
        }
    }
}

// ---------------- Fused: gemm1 (even blocks) + count+slot (odd blocks) -----
__global__ void k_gemm1_count(const float* __restrict__ X, const float* __restrict__ W,
                              float* __restrict__ H, const int* __restrict__ dst) {
    __shared__ GemmSmem s;
    int bid = blockIdx.x >> 1;
    if ((blockIdx.x & 1) == 0) {
        gemm_body(s, X, W, H, bid);
    } else {
        // count: 4 edges per thread via int4; record slot per edge
        int base = (bid * 256 + threadIdx.x) * 4;
        if (base + 3 < N_EDGES) {
            int4 d4 = *(const int4*)(dst + base);
            int4 s4;
            s4.x = atomicAdd(&g_cnt[d4.x], 1);
            s4.y = atomicAdd(&g_cnt[d4.y], 1);
            s4.z = atomicAdd(&g_cnt[d4.z], 1);
            s4.w = atomicAdd(&g_cnt[d4.w], 1);
            *(int4*)(g_slot + base) = s4;
        } else {
            for (int e = base; e < N_EDGES; e++)
                g_slot[e] = atomicAdd(&g_cnt[dst[e]], 1);
        }
    }
}

// ---------------- Single-kernel scan (redundant-prefix, no inter-block dep) -
#define SCAN_CHUNK 512
#define NB_SCAN ((N_NODES + SCAN_CHUNK - 1) / SCAN_CHUNK)   // 98
__global__ void k_scan() {
    __shared__ int tmp[SCAN_CHUNK];
    int b = blockIdx.x, t = threadIdx.x;

    // 1) exclusive base: sum of all counts before this chunk (redundant reads)
    int part = 0;
    for (int i = t; i < b * SCAN_CHUNK; i += SCAN_CHUNK) part += g_cnt[i];
    tmp[t] = part;
    __syncthreads();
    #pragma unroll
    for (int off = SCAN_CHUNK / 2; off > 0; off >>= 1) {
        if (t < off) tmp[t] += tmp[t + off];
        __syncthreads();
    }
    int base = tmp[0];
    __syncthreads();

    // 2) inclusive scan of own chunk
    int i = b * SCAN_CHUNK + t;
    int v = (i < N_NODES) ? g_cnt[i] : 0;
    tmp[t] = v;
    __syncthreads();
    #pragma unroll
    for (int off = 1; off < SCAN_CHUNK; off <<= 1) {
        int x = (t >= off) ? tmp[t - off] : 0;
        __syncthreads();
        tmp[t] += x;
        __syncthreads();
    }
    if (i < N_NODES) {
        g_rowptr[i + 1] = base + tmp[t];
        if (i == 0) g_rowptr[0] = 0;
        g_dinv[i] = rsqrtf((float)v + 1.0f);
        g_cnt[i] = 0;                          // ready for next replay
    }
}

// ---------------- Fill (atomic-free, interleaved CSR) ----------------------
__global__ void k_fill(const int* __restrict__ src, const int* __restrict__ dst) {
    int base = (blockIdx.x * 256 + threadIdx.x) * 4;
    if (base + 3 < N_EDGES) {
        int4 s4 = *(const int4*)(src + base);
        int4 d4 = *(const int4*)(dst + base);
        int4 sl = *(const int4*)(g_slot + base);
        #pragma unroll
        for (int j = 0; j < 4; j++) {
            int s = (&s4.x)[j], d = (&d4.x)[j], slot = (&sl.x)[j];
            float nm = g_dinv[s] * g_dinv[d];
            g_csr[g_rowptr[d] + slot] = make_int2(s, __float_as_int(nm));
        }
    } else {
        for (int e = base; e < N_EDGES; e++) {
            int s = src[e], d = dst[e];
            float nm = g_dinv[s] * g_dinv[d];
            g_csr[g_rowptr[d] + g_slot[e]] = make_int2(s, __float_as_int(nm));
        }
    }
}

// ---------------- GEMM standalone (layer 2) --------------------------------
__global__ void k_gemm(const float* __restrict__ X, const float* __restrict__ W,
                       float* __restrict__ H) {
    __shared__ GemmSmem s;
    gemm_body(s, X, W, H, blockIdx.x);
}

// ---------------- Aggregation (gather via CSR, no float atomics) -----------
__global__ void k_agg(const float* __restrict__ H, const float* __restrict__ bias,
                      float* __restrict__ Z, int relu_out) {
    int node = blockIdx.x * (blockDim.x >> 5) + (threadIdx.x >> 5);
    int lane = threadIdx.x & 31;
    if (node >= N_NODES) return;
    const float4* H4 = (const float4*)H;
    float di = g_dinv[node];
    float sl = di * di;
    float4 acc = H4[node * 32 + lane];
    acc.x *= sl; acc.y *= sl; acc.z *= sl; acc.w *= sl;
    int e0 = g_rowptr[node], e1 = g_rowptr[node + 1];
    #pragma unroll 4
    for (int e = e0; e < e1; e++) {
        int2 pr = g_csr[e];
        float nm = __int_as_float(pr.y);
        float4 v = H4[pr.x * 32 + lane];
        acc.x = fmaf(v.x, nm, acc.x);
        acc.y = fmaf(v.y, nm, acc.y);
        acc.z = fmaf(v.z, nm, acc.z);
        acc.w = fmaf(v.w, nm, acc.w);
    }
    float4 b = ((const float4*)bias)[lane];
    acc.x += b.x; acc.y += b.y; acc.z += b.z; acc.w += b.w;
    if (relu_out) {
        acc.x = fmaxf(acc.x, 0.f); acc.y = fmaxf(acc.y, 0.f);
        acc.z = fmaxf(acc.z, 0.f); acc.w = fmaxf(acc.w, 0.f);
    }
    ((float4*)Z)[node * 32 + lane] = acc;
}

// ---------------- Scores (pos + neg fused) ---------------------------------
__global__ void k_score2(const float* __restrict__ Z, const int* __restrict__ pos,
                         const int* __restrict__ neg, float* __restrict__ out) {
    int i = blockIdx.x * (blockDim.x >> 5) + (threadIdx.x >> 5);
    int lane = threadIdx.x & 31;
    if (i >= 2 * N_EVAL) return;
    const int* idx = (i < N_EVAL) ? pos : neg;
    int j = (i < N_EVAL) ? i : i - N_EVAL;
    int a = idx[j], b = idx[N_EVAL + j];
    const float4* Z4 = (const float4*)Z;
    float4 va = Z4[a * 32 + lane];
    float4 vb = Z4[b * 32 + lane];
    float s = va.x * vb.x + va.y * vb.y + va.z * vb.z + va.w * vb.w;
    #pragma unroll
    for (int off = 16; off; off >>= 1) s += __shfl_xor_sync(0xFFFFFFFFu, s, off);
    if (lane == 0) out[i] = s;
}

// ---------------- launch ---------------------------------------------------
extern "C" void kernel_launch(void* const* d_in, const int* in_sizes, int n_in,
                              void* d_out, int out_size) {
    const float* x   = (const float*)d_in[0];
    const float* W1  = (const float*)d_in[1];
    const float* b1  = (const float*)d_in[2];
    const float* W2  = (const float*)d_in[3];
    const float* b2  = (const float*)d_in[4];
    const int* ei    = (const int*)d_in[5];
    const int* pos   = (const int*)d_in[6];
    const int* neg   = (const int*)d_in[7];
    float* out = (float*)d_out;

    const int* src = ei;
    const int* dst = ei + N_EDGES;

    float *bufA, *bufB;
    cudaGetSymbolAddress((void**)&bufA, g_bufA);
    cudaGetSymbolAddress((void**)&bufB, g_bufB);

    int agg_grid = (N_NODES + 7) / 8;       // 8 warps/block
    int sc_grid = (2 * N_EVAL + 7) / 8;
    int fill_grid = (N_EDGES / 4 + 255) / 256;   // 782

    // (1) gemm1 overlapped with edge counting + slot recording
    k_gemm1_count<<<2 * GEMM_GRID, 256>>>(x, W1, bufA, dst);
    // (2) scan -> rowptr + dinv (+ zero g_cnt)
    k_scan<<<NB_SCAN, SCAN_CHUNK>>>();
    // (3) CSR fill (atomic-free)
    k_fill<<<fill_grid, 256>>>(src, dst);
    // (4) Layer 1 aggregation
    k_agg<<<agg_grid, 256>>>(bufA, b1, bufB, 1);
    // (5) Layer 2 GEMM
    k_gemm<<<GEMM_GRID, 256>>>(bufB, W2, bufA);
    // (6) Layer 2 aggregation
    k_agg<<<agg_grid, 256>>>(bufA, b2, bufB, 0);
    // (7) Scores
    k_score2<<<sc_grid, 256>>>(bufB, pos, neg, out);
}

// round 5
// speedup vs baseline: 1.2445x; 1.0350x over previous
#include <cuda_runtime.h>
#include <cuda_bf16.h>

#define N_NODES 50000
#define D 128
#define N_EDGES 800000
#define N_EVAL 100000

// ---------------- scratch (device globals; no allocation allowed) ----------
__device__ float g_bufA[N_NODES * D];   // GEMM outputs (h1, then h2)
__device__ float g_bufB[N_NODES * D];   // agg outputs (z1, then z2)
__device__ float g_dinv[N_NODES];
__device__ int   g_cnt[N_NODES];        // zeroed by k_scan each run
__device__ int   g_rowptr[N_NODES + 1];
__device__ int   g_slot[N_EDGES];       // per-edge slot from count phase
__device__ int2  g_csr[N_EDGES];        // interleaved {src, norm_bits}

// ---------------- f32x2 helpers --------------------------------------------
__device__ __forceinline__ void ffma2(unsigned long long& d, unsigned long long a,
                                      unsigned long long b) {
    asm("fma.rn.f32x2 %0, %1, %2, %0;" : "+l"(d) : "l"(a), "l"(b));
}
__device__ __forceinline__ unsigned long long pack2(float x) {
    unsigned long long r;
    asm("mov.b64 %0, {%1, %1};" : "=l"(r) : "f"(x));
    return r;
}
__device__ __forceinline__ void unpack2(float& lo, float& hi, unsigned long long v) {
    asm("mov.b64 {%0, %1}, %2;" : "=f"(lo), "=f"(hi) : "l"(v));
}

// ---------------- GEMM device body (f32x2 FFMA2) ---------------------------
#define TM 64
#define KC 32
#define XT_PITCH 66
#define GEMM_GRID ((N_NODES + TM - 1) / TM)     // 782

struct GemmSmem {
    float Xt[KC][XT_PITCH];
    float Ws[KC][D];
};

__device__ __forceinline__ void gemm_body(GemmSmem& s,
                                          const float* __restrict__ X,
                                          const float* __restrict__ W,
                                          float* __restrict__ H, int bid) {
    int row0 = bid * TM;
    int tid = threadIdx.x;                // 256 threads
    int tx = tid & 31;                    // column group: 4 cols each
    int ty = tid >> 5;                    // row group: 8 rows each
    unsigned long long acc[4][4];
    #pragma unroll
    for (int p = 0; p < 4; p++)
        #pragma unroll
        for (int c = 0; c < 4; c++) acc[p][c] = 0ull;

    for (int k0 = 0; k0 < D; k0 += KC) {
        for (int i = tid; i < (TM * KC) / 4; i += 256) {
            int r = i >> 3;               // 0..63
            int c4 = i & 7;               // 0..7
            int gr = row0 + r;
            float4 v = (gr < N_NODES) ? *(const float4*)(X + gr * D + k0 + c4 * 4)
                                      : make_float4(0.f, 0.f, 0.f, 0.f);
            s.Xt[c4 * 4 + 0][r] = v.x;
            s.Xt[c4 * 4 + 1][r] = v.y;
            s.Xt[c4 * 4 + 2][r] = v.z;
            s.Xt[c4 * 4 + 3][r] = v.w;
        }
        for (int i = tid; i < (KC * D) / 4; i += 256) {
            int r = i >> 5, c4 = i & 31;
            *(float4*)&s.Ws[r][c4 * 4] = *(const float4*)(W + (k0 + r) * D + c4 * 4);
        }
        __syncthreads();
        #pragma unroll
        for (int k = 0; k < KC; k++) {
            float4 b4 = *(const float4*)&s.Ws[k][tx * 4];
            unsigned long long b0 = pack2(b4.x), b1 = pack2(b4.y);
            unsigned long long b2 = pack2(b4.z), b3 = pack2(b4.w);
            #pragma unroll
            for (int p = 0; p < 4; p++) {
                unsigned long long a =
                    *(const unsigned long long*)&s.Xt[k][ty * 8 + 2 * p];
                ffma2(acc[p][0], a, b0);
                ffma2(acc[p][1], a, b1);
                ffma2(acc[p][2], a, b2);
                ffma2(acc[p][3], a, b3);
            }
        }
        __syncthreads();
    }
    #pragma unroll
    for (int p = 0; p < 4; p++) {
        float lo0, hi0, lo1, hi1, lo2, hi2, lo3, hi3;
        unpack2(lo0, hi0, acc[p][0]);
        unpack2(lo1, hi1, acc[p][1]);
        unpack2(lo2, hi2, acc[p][2]);
        unpack2(lo3, hi3, acc[p][3]);
        int gr0 = row0 + ty * 8 + 2 * p;
        if (gr0 < N_NODES) {
            float4 v = {lo0, lo1, lo2, lo3};
            *(float4*)(H + gr0 * D + tx * 4) = v;
        }
        if (gr0 + 1 < N_NODES) {
            float4 v = {hi0, hi1, hi2, hi3};
            *(float4*)(H + (gr0 + 1) * D + tx * 4) = v;
        }
    }
}

// ---------------- Fused: gemm1 (even blocks) + count+slot (odd blocks) -----
__global__ void k_gemm1_count(const float* __restrict__ X, const float* __restrict__ W,
                              float* __restrict__ H, const int* __restrict__ dst) {
    __shared__ GemmSmem s;
    int bid = blockIdx.x >> 1;
    if ((blockIdx.x & 1) == 0) {
        gemm_body(s, X, W, H, bid);
    } else {
        // count: 4 edges per thread via int4; record slot per edge
        int base = (bid * 256 + threadIdx.x) * 4;
        if (base + 3 < N_EDGES) {
            int4 d4 = *(const int4*)(dst + base);
            int4 s4;
            s4.x = atomicAdd(&g_cnt[d4.x], 1);
            s4.y = atomicAdd(&g_cnt[d4.y], 1);
            s4.z = atomicAdd(&g_cnt[d4.z], 1);
            s4.w = atomicAdd(&g_cnt[d4.w], 1);
            *(int4*)(g_slot + base) = s4;
        } else {
            for (int e = base; e < N_EDGES; e++)
                g_slot[e] = atomicAdd(&g_cnt[dst[e]], 1);
        }
    }
}

// ---------------- Single-kernel scan (redundant-prefix, no inter-block dep) -
#define SCAN_CHUNK 512
#define NB_SCAN ((N_NODES + SCAN_CHUNK - 1) / SCAN_CHUNK)   // 98
__global__ void k_scan() {
    __shared__ int tmp[SCAN_CHUNK];
    int b = blockIdx.x, t = threadIdx.x;

    // 1) exclusive base: sum of all counts before this chunk (redundant reads)
    int part = 0;
    for (int i = t; i < b * SCAN_CHUNK; i += SCAN_CHUNK) part += g_cnt[i];
    tmp[t] = part;
    __syncthreads();
    #pragma unroll
    for (int off = SCAN_CHUNK / 2; off > 0; off >>= 1) {
        if (t < off) tmp[t] += tmp[t + off];
        __syncthreads();
    }
    int base = tmp[0];
    __syncthreads();

    // 2) inclusive scan of own chunk
    int i = b * SCAN_CHUNK + t;
    int v = (i < N_NODES) ? g_cnt[i] : 0;
    tmp[t] = v;
    __syncthreads();
    #pragma unroll
    for (int off = 1; off < SCAN_CHUNK; off <<= 1) {
        int x = (t >= off) ? tmp[t - off] : 0;
        __syncthreads();
        tmp[t] += x;
        __syncthreads();
    }
    if (i < N_NODES) {
        g_rowptr[i + 1] = base + tmp[t];
        if (i == 0) g_rowptr[0] = 0;
        g_dinv[i] = rsqrtf((float)v + 1.0f);
        g_cnt[i] = 0;                          // ready for next replay
    }
}

// ---------------- Fill (atomic-free, interleaved CSR) ----------------------
__global__ void k_fill(const int* __restrict__ src, const int* __restrict__ dst) {
    int base = (blockIdx.x * 256 + threadIdx.x) * 4;
    if (base + 3 < N_EDGES) {
        int4 s4 = *(const int4*)(src + base);
        int4 d4 = *(const int4*)(dst + base);
        int4 sl = *(const int4*)(g_slot + base);
        #pragma unroll
        for (int j = 0; j < 4; j++) {
            int s = (&s4.x)[j], d = (&d4.x)[j], slot = (&sl.x)[j];
            float nm = g_dinv[s] * g_dinv[d];
            g_csr[g_rowptr[d] + slot] = make_int2(s, __float_as_int(nm));
        }
    } else {
        for (int e = base; e < N_EDGES; e++) {
            int s = src[e], d = dst[e];
            float nm = g_dinv[s] * g_dinv[d];
            g_csr[g_rowptr[d] + g_slot[e]] = make_int2(s, __float_as_int(nm));
        }
    }
}

// ---------------- GEMM standalone (layer 2) --------------------------------
__global__ void k_gemm(const float* __restrict__ X, const float* __restrict__ W,
                       float* __restrict__ H) {
    __shared__ GemmSmem s;
    gemm_body(s, X, W, H, blockIdx.x);
}

// ---------------- Aggregation: 4-edge pipelined gather ---------------------
__global__ void k_agg(const float* __restrict__ H, const float* __restrict__ bias,
                      float* __restrict__ Z, int relu_out) {
    int node = blockIdx.x * (blockDim.x >> 5) + (threadIdx.x >> 5);
    int lane = threadIdx.x & 31;
    if (node >= N_NODES) return;
    const float4* H4 = (const float4*)H;
    float di = g_dinv[node];
    float sl = di * di;
    float4 acc = H4[node * 32 + lane];
    acc.x *= sl; acc.y *= sl; acc.z *= sl; acc.w *= sl;
    int e = g_rowptr[node], e1 = g_rowptr[node + 1];

    // 4-wide batches: 4 independent csr loads, then 4 independent H gathers
    for (; e + 4 <= e1; e += 4) {
        int2 p0 = g_csr[e + 0];
        int2 p1 = g_csr[e + 1];
        int2 p2 = g_csr[e + 2];
        int2 p3 = g_csr[e + 3];
        float4 v0 = H4[p0.x * 32 + lane];
        float4 v1 = H4[p1.x * 32 + lane];
        float4 v2 = H4[p2.x * 32 + lane];
        float4 v3 = H4[p3.x * 32 + lane];
        float n0 = __int_as_float(p0.y), n1 = __int_as_float(p1.y);
        float n2 = __int_as_float(p2.y), n3 = __int_as_float(p3.y);
        acc.x = fmaf(v0.x, n0, acc.x); acc.y = fmaf(v0.y, n0, acc.y);
        acc.z = fmaf(v0.z, n0, acc.z); acc.w = fmaf(v0.w, n0, acc.w);
        acc.x = fmaf(v1.x, n1, acc.x); acc.y = fmaf(v1.y, n1, acc.y);
        acc.z = fmaf(v1.z, n1, acc.z); acc.w = fmaf(v1.w, n1, acc.w);
        acc.x = fmaf(v2.x, n2, acc.x); acc.y = fmaf(v2.y, n2, acc.y);
        acc.z = fmaf(v2.z, n2, acc.z); acc.w = fmaf(v2.w, n2, acc.w);
        acc.x = fmaf(v3.x, n3, acc.x); acc.y = fmaf(v3.y, n3, acc.y);
        acc.z = fmaf(v3.z, n3, acc.z); acc.w = fmaf(v3.w, n3, acc.w);
    }
    for (; e < e1; e++) {
        int2 pr = g_csr[e];
        float nm = __int_as_float(pr.y);
        float4 v = H4[pr.x * 32 + lane];
        acc.x = fmaf(v.x, nm, acc.x);
        acc.y = fmaf(v.y, nm, acc.y);
        acc.z = fmaf(v.z, nm, acc.z);
        acc.w = fmaf(v.w, nm, acc.w);
    }
    float4 b = ((const float4*)bias)[lane];
    acc.x += b.x; acc.y += b.y; acc.z += b.z; acc.w += b.w;
    if (relu_out) {
        acc.x = fmaxf(acc.x, 0.f); acc.y = fmaxf(acc.y, 0.f);
        acc.z = fmaxf(acc.z, 0.f); acc.w = fmaxf(acc.w, 0.f);
    }
    ((float4*)Z)[node * 32 + lane] = acc;
}

// ---------------- Scores: 4 pairs per warp (MLP 8) -------------------------
// N_EVAL % 4 == 0 so a 4-group never straddles the pos/neg boundary.
__global__ void k_score2(const float* __restrict__ Z, const int* __restrict__ pos,
                         const int* __restrict__ neg, float* __restrict__ out) {
    int w = blockIdx.x * (blockDim.x >> 5) + (threadIdx.x >> 5);
    int lane = threadIdx.x & 31;
    int i0 = w * 4;
    if (i0 >= 2 * N_EVAL) return;
    const int* idx = (i0 < N_EVAL) ? pos : neg;
    int j0 = (i0 < N_EVAL) ? i0 : i0 - N_EVAL;
    int4 a4 = *(const int4*)(idx + j0);
    int4 b4 = *(const int4*)(idx + N_EVAL + j0);
    const float4* Z4 = (const float4*)Z;
    float4 va0 = Z4[a4.x * 32 + lane];
    float4 va1 = Z4[a4.y * 32 + lane];
    float4 va2 = Z4[a4.z * 32 + lane];
    float4 va3 = Z4[a4.w * 32 + lane];
    float4 vb0 = Z4[b4.x * 32 + lane];
    float4 vb1 = Z4[b4.y * 32 + lane];
    float4 vb2 = Z4[b4.z * 32 + lane];
    float4 vb3 = Z4[b4.w * 32 + lane];
    float s0 = va0.x * vb0.x + va0.y * vb0.y + va0.z * vb0.z + va0.w * vb0.w;
    float s1 = va1.x * vb1.x + va1.y * vb1.y + va1.z * vb1.z + va1.w * vb1.w;
    float s2 = va2.x * vb2.x + va2.y * vb2.y + va2.z * vb2.z + va2.w * vb2.w;
    float s3 = va3.x * vb3.x + va3.y * vb3.y + va3.z * vb3.z + va3.w * vb3.w;
    #pragma unroll
    for (int off = 16; off; off >>= 1) {
        s0 += __shfl_xor_sync(0xFFFFFFFFu, s0, off);
        s1 += __shfl_xor_sync(0xFFFFFFFFu, s1, off);
        s2 += __shfl_xor_sync(0xFFFFFFFFu, s2, off);
        s3 += __shfl_xor_sync(0xFFFFFFFFu, s3, off);
    }
    if (lane == 0) *(float4*)(out + i0) = make_float4(s0, s1, s2, s3);
}

// ---------------- launch ---------------------------------------------------
extern "C" void kernel_launch(void* const* d_in, const int* in_sizes, int n_in,
                              void* d_out, int out_size) {
    const float* x   = (const float*)d_in[0];
    const float* W1  = (const float*)d_in[1];
    const float* b1  = (const float*)d_in[2];
    const float* W2  = (const float*)d_in[3];
    const float* b2  = (const float*)d_in[4];
    const int* ei    = (const int*)d_in[5];
    const int* pos   = (const int*)d_in[6];
    const int* neg   = (const int*)d_in[7];
    float* out = (float*)d_out;

    const int* src = ei;
    const int* dst = ei + N_EDGES;

    float *bufA, *bufB;
    cudaGetSymbolAddress((void**)&bufA, g_bufA);
    cudaGetSymbolAddress((void**)&bufB, g_bufB);

    int agg_grid = (N_NODES + 7) / 8;            // 8 warps/block
    int sc_grid = (2 * N_EVAL / 4 + 7) / 8;      // 4 pairs per warp
    int fill_grid = (N_EDGES / 4 + 255) / 256;   // 782

    // (1) gemm1 overlapped with edge counting + slot recording
    k_gemm1_count<<<2 * GEMM_GRID, 256>>>(x, W1, bufA, dst);
    // (2) scan -> rowptr + dinv (+ zero g_cnt)
    k_scan<<<NB_SCAN, SCAN_CHUNK>>>();
    // (3) CSR fill (atomic-free)
    k_fill<<<fill_grid, 256>>>(src, dst);
    // (4) Layer 1 aggregation
    k_agg<<<agg_grid, 256>>>(bufA, b1, bufB, 1);
    // (5) Layer 2 GEMM
    k_gemm<<<GEMM_GRID, 256>>>(bufB, W2, bufA);
    // (6) Layer 2 aggregation
    k_agg<<<agg_grid, 256>>>(bufA, b2, bufB, 0);
    // (7) Scores
    k_score2<<<sc_grid, 256>>>(bufB, pos, neg, out);
}